// round 9
// baseline (speedup 1.0000x reference)
#include <cuda_runtime.h>

#define B_ 4
#define H_ 8
#define N_ 256
#define DQ 80
#define DNK 64
#define DEK 16
#define DV 64
#define TQ 8
#define NTHREADS 256
#define ATT_STRIDE 257

__global__ __launch_bounds__(NTHREADS, 3)
void edge_attn_kernel(const float* __restrict__ q,
                      const float* __restrict__ nk,
                      const float* __restrict__ ek,
                      const float* __restrict__ v,
                      const int*   __restrict__ mask,
                      float* __restrict__ out,       // [B,H,N,DV]
                      float* __restrict__ attn_out)  // [B,H,N,N]
{
    __shared__ float s_qT[DQ * TQ];            // q tile transposed: [d][qq]
    __shared__ float s_attn[TQ * ATT_STRIDE];  // logits

    const int tid = threadIdx.x;
    const int qt  = blockIdx.x;
    const int h   = blockIdx.y;
    const int b   = blockIdx.z;
    const int bh  = b * H_ + h;
    const int q0  = qt * TQ;
    const int k   = tid;  // one thread per key

    // ---- issue first ek loads (cold HBM stream) before the sync ----
    const float4* ekp = (const float4*)(ek + (size_t)((bh * N_ + q0) * N_ + k) * DEK);
    float4 e0 = ekp[0], e1 = ekp[1], e2 = ekp[2], e3 = ekp[3];

    // ---- Phase A: q tile transposed into smem ----
    const float* qbase = q + (size_t)(bh * N_ + q0) * DQ;
    for (int i = tid; i < TQ * DQ; i += NTHREADS) {
        int qq = i / DQ;
        int d  = i - qq * DQ;
        s_qT[d * TQ + qq] = qbase[qq * DQ + d];
    }
    __syncthreads();

    float acc[TQ];

    // ---- Phase B1: edge logits (ek read once, prefetch one qq ahead) ----
#define QE(d) s_qT[(DNK + (d)) * TQ + qq]
#pragma unroll
    for (int qq = 0; qq < TQ; qq++) {
        float4 f0 = e0, f1 = e1, f2 = e2, f3 = e3;
        if (qq < TQ - 1) {
            const float4* e = ekp + (qq + 1) * (N_ * DEK / 4);
            e0 = e[0]; e1 = e[1]; e2 = e[2]; e3 = e[3];
        }
        float s0, s1;
        s0  = f0.x * QE(0);
        s0 += f0.y * QE(1);
        s0 += f0.z * QE(2);
        s0 += f0.w * QE(3);
        s0 += f1.x * QE(4);
        s0 += f1.y * QE(5);
        s0 += f1.z * QE(6);
        s0 += f1.w * QE(7);
        s1  = f2.x * QE(8);
        s1 += f2.y * QE(9);
        s1 += f2.z * QE(10);
        s1 += f2.w * QE(11);
        s1 += f3.x * QE(12);
        s1 += f3.y * QE(13);
        s1 += f3.z * QE(14);
        s1 += f3.w * QE(15);
        acc[qq] = s0 + s1;
    }
#undef QE

    // ---- Phase B2: node logits, nk streamed from L2 in float4 chunks ----
    {
        const float4* nkp  = (const float4*)(nk + (size_t)(bh * N_ + k) * DNK);
        const float4* sqT4 = (const float4*)s_qT;  // row d = 2 float4 at index d*2
#pragma unroll
        for (int i = 0; i < 16; i++) {
            float4 nv4 = nkp[i];
#pragma unroll
            for (int c = 0; c < 4; c++) {
                int d = i * 4 + c;
                float nv = (c == 0) ? nv4.x : (c == 1) ? nv4.y : (c == 2) ? nv4.z : nv4.w;
                float4 qa = sqT4[d * 2 + 0];
                float4 qb = sqT4[d * 2 + 1];
                acc[0] += nv * qa.x;  acc[1] += nv * qa.y;
                acc[2] += nv * qa.z;  acc[3] += nv * qa.w;
                acc[4] += nv * qb.x;  acc[5] += nv * qb.y;
                acc[6] += nv * qb.z;  acc[7] += nv * qb.w;
            }
        }
    }

    // ---- mask + temperature -> smem logits ----
    {
        const int* mrow = mask + (size_t)(b * N_ + q0) * N_ + k;
#pragma unroll
        for (int qq = 0; qq < TQ; qq++) {
            int m = mrow[qq * N_];
            float logit = acc[qq] * 0.125f;
            s_attn[qq * ATT_STRIDE + k] = (m == 0) ? -1000000000.0f : logit;
        }
    }
    __syncthreads();

    // ---- Phase C: softmax, one warp per row; probs stay in registers ----
    const int w    = tid >> 5;
    const int lane = tid & 31;
    float vals[8];
    {
        float* row = s_attn + w * ATT_STRIDE;
        float mx = -3.4e38f;
#pragma unroll
        for (int i = 0; i < 8; i++) {
            vals[i] = row[lane + 32 * i];
            mx = fmaxf(mx, vals[i]);
        }
#pragma unroll
        for (int off = 16; off; off >>= 1)
            mx = fmaxf(mx, __shfl_xor_sync(0xffffffffu, mx, off));
        float sum = 0.f;
#pragma unroll
        for (int i = 0; i < 8; i++) {
            float e = __expf(vals[i] - mx);
            vals[i] = e;
            sum += e;
        }
#pragma unroll
        for (int off = 16; off; off >>= 1)
            sum += __shfl_xor_sync(0xffffffffu, sum, off);
        float inv = 1.0f / sum;
        float* attn_g = attn_out + (size_t)(bh * N_ + q0 + w) * N_;
#pragma unroll
        for (int i = 0; i < 8; i++) {
            float p = vals[i] * inv;
            vals[i] = p;
            attn_g[lane + 32 * i] = p;
        }
    }

    // ---- Phase D: AV via warp shuffle broadcast, lane owns 2 dims ----
    {
        const float* vbase = v + (size_t)(bh * N_) * DV + lane * 2;
        float ox = 0.f, oy = 0.f;
#pragma unroll
        for (int i = 0; i < 8; i++) {
            float p = vals[i];
#pragma unroll 4
            for (int src = 0; src < 32; src++) {
                float a = __shfl_sync(0xffffffffu, p, src);
                float2 vv = *(const float2*)(vbase + (size_t)(32 * i + src) * DV);
                ox += a * vv.x;
                oy += a * vv.y;
            }
        }
        float2* op = (float2*)(out + (size_t)(bh * N_ + q0 + w) * DV + lane * 2);
        *op = make_float2(ox, oy);
    }
}

extern "C" void kernel_launch(void* const* d_in, const int* in_sizes, int n_in,
                              void* d_out, int out_size)
{
    const float* q    = (const float*)d_in[0];
    const float* nk   = (const float*)d_in[1];
    const float* ek   = (const float*)d_in[2];
    const float* v    = (const float*)d_in[3];
    const int*   mask = (const int*)d_in[4];

    float* out  = (float*)d_out;                         // [4,8,256,64]
    float* attn = out + (size_t)B_ * H_ * N_ * DV;       // [4,8,256,256]

    dim3 grid(N_ / TQ, H_, B_);
    edge_attn_kernel<<<grid, NTHREADS>>>(q, nk, ek, v, mask, out, attn);
}

// round 11
// speedup vs baseline: 1.4683x; 1.4683x over previous
#include <cuda_runtime.h>

#define B_ 4
#define H_ 8
#define N_ 256
#define DQ 80
#define DNK 64
#define DEK 16
#define DV 64
#define TQ 16
#define NTHREADS 256
#define ATT_STRIDE 257

typedef unsigned long long ull;

__device__ __forceinline__ ull pk2(float lo, float hi) {
    ull r; asm("mov.b64 %0, {%1, %2};" : "=l"(r) : "f"(lo), "f"(hi)); return r;
}
__device__ __forceinline__ void upk2(ull p, float& lo, float& hi) {
    asm("mov.b64 {%0, %1}, %2;" : "=f"(lo), "=f"(hi) : "l"(p));
}
__device__ __forceinline__ ull fma2(ull a, ull b, ull c) {
    ull d; asm("fma.rn.f32x2 %0, %1, %2, %3;" : "=l"(d) : "l"(a), "l"(b), "l"(c)); return d;
}

__global__ __launch_bounds__(NTHREADS, 3)
void edge_attn_kernel(const float* __restrict__ q,
                      const float* __restrict__ nk,
                      const float* __restrict__ ek,
                      const float* __restrict__ v,
                      const int*   __restrict__ mask,
                      float* __restrict__ out,       // [B,H,N,DV]
                      float* __restrict__ attn_out)  // [B,H,N,N]
{
    __shared__ float s_qT[DQ * TQ];            // q tile transposed: [d][qq], qq contiguous
    __shared__ float s_attn[TQ * ATT_STRIDE];  // logits -> probs

    const int tid = threadIdx.x;
    const int qt  = blockIdx.x;
    const int h   = blockIdx.y;
    const int b   = blockIdx.z;
    const int bh  = b * H_ + h;
    const int q0  = qt * TQ;
    const int k   = tid;  // one thread per key

    // ---- issue first ek loads (cold HBM stream) before the sync ----
    const float4* ekp = (const float4*)(ek + (size_t)((bh * N_ + q0) * N_ + k) * DEK);
    float4 e0 = ekp[0], e1 = ekp[1], e2 = ekp[2], e3 = ekp[3];

    // ---- Phase A: q tile transposed into smem ----
    const float* qbase = q + (size_t)(bh * N_ + q0) * DQ;
    for (int i = tid; i < TQ * DQ; i += NTHREADS) {
        int qq = i / DQ;
        int d  = i - qq * DQ;
        s_qT[d * TQ + qq] = qbase[qq * DQ + d];
    }
    __syncthreads();

    float acc[TQ];

    // ---- Phase B1: edge logits (ek read once from HBM, prefetch one qq ahead) ----
#define QE(d) s_qT[(DNK + (d)) * TQ + qq]
#pragma unroll
    for (int qq = 0; qq < TQ; qq++) {
        float4 f0 = e0, f1 = e1, f2 = e2, f3 = e3;
        if (qq < TQ - 1) {
            const float4* e = ekp + (qq + 1) * (N_ * DEK / 4);
            e0 = e[0]; e1 = e[1]; e2 = e[2]; e3 = e[3];
        }
        float s0, s1;
        s0  = f0.x * QE(0);
        s0 += f0.y * QE(1);
        s0 += f0.z * QE(2);
        s0 += f0.w * QE(3);
        s0 += f1.x * QE(4);
        s0 += f1.y * QE(5);
        s0 += f1.z * QE(6);
        s0 += f1.w * QE(7);
        s1  = f2.x * QE(8);
        s1 += f2.y * QE(9);
        s1 += f2.z * QE(10);
        s1 += f2.w * QE(11);
        s1 += f3.x * QE(12);
        s1 += f3.y * QE(13);
        s1 += f3.z * QE(14);
        s1 += f3.w * QE(15);
        acc[qq] = s0 + s1;
    }
#undef QE

    // pack edge results into f32x2 accumulators (qq pairs)
    ull acc2[TQ / 2];
#pragma unroll
    for (int j = 0; j < TQ / 2; j++) acc2[j] = pk2(acc[2 * j], acc[2 * j + 1]);

    // ---- Phase B2: node logits, nk streamed from L2, f32x2 packed FMA ----
    {
        const float4* nkp = (const float4*)(nk + (size_t)(bh * N_ + k) * DNK);
        // s_qT row d = 16 floats = 4x ulonglong2; each .x/.y is a packed qq-pair
        const ulonglong2* sq2 = (const ulonglong2*)s_qT;
#pragma unroll
        for (int i = 0; i < 16; i++) {
            float4 nv4 = nkp[i];
#pragma unroll
            for (int c = 0; c < 4; c++) {
                int d = i * 4 + c;
                float nv = (c == 0) ? nv4.x : (c == 1) ? nv4.y : (c == 2) ? nv4.z : nv4.w;
                ull nv2 = pk2(nv, nv);
                ulonglong2 u0 = sq2[d * 4 + 0];
                ulonglong2 u1 = sq2[d * 4 + 1];
                ulonglong2 u2 = sq2[d * 4 + 2];
                ulonglong2 u3 = sq2[d * 4 + 3];
                acc2[0] = fma2(nv2, u0.x, acc2[0]);
                acc2[1] = fma2(nv2, u0.y, acc2[1]);
                acc2[2] = fma2(nv2, u1.x, acc2[2]);
                acc2[3] = fma2(nv2, u1.y, acc2[3]);
                acc2[4] = fma2(nv2, u2.x, acc2[4]);
                acc2[5] = fma2(nv2, u2.y, acc2[5]);
                acc2[6] = fma2(nv2, u3.x, acc2[6]);
                acc2[7] = fma2(nv2, u3.y, acc2[7]);
            }
        }
#pragma unroll
        for (int j = 0; j < TQ / 2; j++) upk2(acc2[j], acc[2 * j], acc[2 * j + 1]);
    }

    // ---- mask + temperature -> smem logits ----
    {
        const int* mrow = mask + (size_t)(b * N_ + q0) * N_ + k;
#pragma unroll
        for (int qq = 0; qq < TQ; qq++) {
            int m = mrow[qq * N_];
            float logit = acc[qq] * 0.125f;
            s_attn[qq * ATT_STRIDE + k] = (m == 0) ? -1000000000.0f : logit;
        }
    }
    __syncthreads();

    // ---- Phase C: softmax, one warp per 2 rows; probs -> smem + gmem ----
    {
        const int warp = tid >> 5, lane = tid & 31;
        float* attn_g = attn_out + (size_t)(bh * N_ + q0) * N_;
#pragma unroll
        for (int r = 0; r < 2; r++) {
            int qq = warp * 2 + r;
            float* row = s_attn + qq * ATT_STRIDE;
            float vals[8];
            float mx = -3.4e38f;
#pragma unroll
            for (int i = 0; i < 8; i++) {
                vals[i] = row[lane + 32 * i];
                mx = fmaxf(mx, vals[i]);
            }
#pragma unroll
            for (int off = 16; off; off >>= 1)
                mx = fmaxf(mx, __shfl_xor_sync(0xffffffffu, mx, off));
            float sum = 0.f;
#pragma unroll
            for (int i = 0; i < 8; i++) {
                float e = __expf(vals[i] - mx);
                vals[i] = e;
                sum += e;
            }
#pragma unroll
            for (int off = 16; off; off >>= 1)
                sum += __shfl_xor_sync(0xffffffffu, sum, off);
            float inv = 1.0f / sum;
#pragma unroll
            for (int i = 0; i < 8; i++) {
                float p = vals[i] * inv;
                row[lane + 32 * i] = p;
                attn_g[qq * N_ + lane + 32 * i] = p;
            }
        }
    }
    __syncthreads();

    // ---- Phase D: out[q][d] = sum_k attn[q][k] * v[k][d], f32x2 packed ----
    {
        const int dg = tid & 15;   // 4 dims each
        const int qq = tid >> 4;   // 1 q-row each
        const float* vrow = v + (size_t)(bh * N_) * DV + dg * 4;
        const float* arow = s_attn + qq * ATT_STRIDE;
        ull o0 = 0, o1 = 0;  // packed zeros (0x0 == {0.f,0.f})
#pragma unroll 4
        for (int kk = 0; kk < N_; kk++) {
            float a = arow[kk];                                       // broadcast LDS
            ull a2 = pk2(a, a);
            ulonglong2 vv = *(const ulonglong2*)(vrow + kk * DV);     // LDG.128, L1-resident
            o0 = fma2(a2, vv.x, o0);
            o1 = fma2(a2, vv.y, o1);
        }
        float4 o;
        upk2(o0, o.x, o.y);
        upk2(o1, o.z, o.w);
        float4* op = (float4*)(out + (size_t)(bh * N_ + q0 + qq) * DV + dg * 4);
        *op = o;
    }
}

extern "C" void kernel_launch(void* const* d_in, const int* in_sizes, int n_in,
                              void* d_out, int out_size)
{
    const float* q    = (const float*)d_in[0];
    const float* nk   = (const float*)d_in[1];
    const float* ek   = (const float*)d_in[2];
    const float* v    = (const float*)d_in[3];
    const int*   mask = (const int*)d_in[4];

    float* out  = (float*)d_out;                         // [4,8,256,64]
    float* attn = out + (size_t)B_ * H_ * N_ * DV;       // [4,8,256,256]

    dim3 grid(N_ / TQ, H_, B_);
    edge_attn_kernel<<<grid, NTHREADS>>>(q, nk, ek, v, mask, out, attn);
}

// round 14
// speedup vs baseline: 2.0443x; 1.3922x over previous
#include <cuda_runtime.h>

#define B_ 4
#define H_ 8
#define N_ 256
#define DQ 80
#define DNK 64
#define DEK 16
#define DV 64
#define TQ 16
#define HQ 8              // qq rows per thread-half
#define NTHREADS 512
#define ATT_STRIDE 257

typedef unsigned long long ull;

__device__ __forceinline__ ull pk2(float lo, float hi) {
    ull r; asm("mov.b64 %0, {%1, %2};" : "=l"(r) : "f"(lo), "f"(hi)); return r;
}
__device__ __forceinline__ void upk2(ull p, float& lo, float& hi) {
    asm("mov.b64 {%0, %1}, %2;" : "=f"(lo), "=f"(hi) : "l"(p));
}
__device__ __forceinline__ ull fma2(ull a, ull b, ull c) {
    ull d; asm("fma.rn.f32x2 %0, %1, %2, %3;" : "=l"(d) : "l"(a), "l"(b), "l"(c)); return d;
}

__global__ __launch_bounds__(NTHREADS, 2)
void edge_attn_kernel(const float* __restrict__ q,
                      const float* __restrict__ nk,
                      const float* __restrict__ ek,
                      const float* __restrict__ v,
                      const int*   __restrict__ mask,
                      float* __restrict__ out,       // [B,H,N,DV]
                      float* __restrict__ attn_out)  // [B,H,N,N]
{
    __shared__ float s_qT[DQ * TQ];            // q tile transposed: [d][qq]
    __shared__ float s_attn[TQ * ATT_STRIDE];  // logits -> probs

    const int tid  = threadIdx.x;
    const int k    = tid & 255;      // key
    const int half = tid >> 8;       // 0: qq 0-7, 1: qq 8-15
    const int qt   = blockIdx.x;
    const int h    = blockIdx.y;
    const int b    = blockIdx.z;
    const int bh   = b * H_ + h;
    const int q0   = qt * TQ;
    const int qh   = q0 + half * HQ; // first global q row for this half

    // ---- issue first ek loads (cold HBM stream) before the sync ----
    const float4* ekp = (const float4*)(ek + (size_t)((bh * N_ + qh) * N_ + k) * DEK);
    float4 e0 = __ldcs(ekp + 0), e1 = __ldcs(ekp + 1),
           e2 = __ldcs(ekp + 2), e3 = __ldcs(ekp + 3);

    // ---- Phase A: q tile transposed into smem ----
    const float* qbase = q + (size_t)(bh * N_ + q0) * DQ;
    for (int i = tid; i < TQ * DQ; i += NTHREADS) {
        int qq = i / DQ;
        int d  = i - qq * DQ;
        s_qT[d * TQ + qq] = qbase[qq * DQ + d];
    }
    __syncthreads();

    float acc[HQ];

    // ---- Phase B1: edge logits for this half's 8 rows (prefetch 1 ahead) ----
#define QE(d) s_qT[(DNK + (d)) * TQ + half * HQ + j]
#pragma unroll
    for (int j = 0; j < HQ; j++) {
        float4 f0 = e0, f1 = e1, f2 = e2, f3 = e3;
        if (j < HQ - 1) {
            const float4* e = ekp + (j + 1) * (N_ * DEK / 4);
            e0 = __ldcs(e + 0); e1 = __ldcs(e + 1);
            e2 = __ldcs(e + 2); e3 = __ldcs(e + 3);
        }
        float s0, s1;
        s0  = f0.x * QE(0);
        s0 += f0.y * QE(1);
        s0 += f0.z * QE(2);
        s0 += f0.w * QE(3);
        s0 += f1.x * QE(4);
        s0 += f1.y * QE(5);
        s0 += f1.z * QE(6);
        s0 += f1.w * QE(7);
        s1  = f2.x * QE(8);
        s1 += f2.y * QE(9);
        s1 += f2.z * QE(10);
        s1 += f2.w * QE(11);
        s1 += f3.x * QE(12);
        s1 += f3.y * QE(13);
        s1 += f3.z * QE(14);
        s1 += f3.w * QE(15);
        acc[j] = s0 + s1;
    }
#undef QE

    // pack into f32x2 accumulators (4 packed pairs for 8 rows)
    ull acc2[HQ / 2];
#pragma unroll
    for (int j = 0; j < HQ / 2; j++) acc2[j] = pk2(acc[2 * j], acc[2 * j + 1]);

    // ---- Phase B2: node logits for this half's rows, nk streamed from L2 ----
    {
        const float4* nkp = (const float4*)(nk + (size_t)(bh * N_ + k) * DNK);
        // s_qT row d floats [8*half .. 8*half+8) = 2x ulonglong2 at index d*4 + 2*half
        const ulonglong2* sq2 = (const ulonglong2*)s_qT;
        const int sbase = 2 * half;
#pragma unroll
        for (int i = 0; i < 16; i++) {
            float4 nv4 = nkp[i];
#pragma unroll
            for (int c = 0; c < 4; c++) {
                int d = i * 4 + c;
                float nv = (c == 0) ? nv4.x : (c == 1) ? nv4.y : (c == 2) ? nv4.z : nv4.w;
                ull nv2 = pk2(nv, nv);
                ulonglong2 u0 = sq2[d * 4 + sbase];
                ulonglong2 u1 = sq2[d * 4 + sbase + 1];
                acc2[0] = fma2(nv2, u0.x, acc2[0]);
                acc2[1] = fma2(nv2, u0.y, acc2[1]);
                acc2[2] = fma2(nv2, u1.x, acc2[2]);
                acc2[3] = fma2(nv2, u1.y, acc2[3]);
            }
        }
#pragma unroll
        for (int j = 0; j < HQ / 2; j++) upk2(acc2[j], acc[2 * j], acc[2 * j + 1]);
    }

    // ---- mask + temperature -> smem logits ----
    {
        const int* mrow = mask + (size_t)(b * N_ + qh) * N_ + k;
#pragma unroll
        for (int j = 0; j < HQ; j++) {
            int m = mrow[j * N_];
            float logit = acc[j] * 0.125f;
            s_attn[(half * HQ + j) * ATT_STRIDE + k] = (m == 0) ? -1000000000.0f : logit;
        }
    }
    __syncthreads();

    // ---- Phase C: softmax, one warp per row (16 warps, 16 rows) ----
    const int w    = tid >> 5;   // 0..15 == row
    const int lane = tid & 31;
    {
        float* row = s_attn + w * ATT_STRIDE;
        float vals[8];
        float mx = -3.4e38f;
#pragma unroll
        for (int i = 0; i < 8; i++) {
            vals[i] = row[lane + 32 * i];
            mx = fmaxf(mx, vals[i]);
        }
#pragma unroll
        for (int off = 16; off; off >>= 1)
            mx = fmaxf(mx, __shfl_xor_sync(0xffffffffu, mx, off));
        float sum = 0.f;
#pragma unroll
        for (int i = 0; i < 8; i++) {
            float e = __expf(vals[i] - mx);
            vals[i] = e;
            sum += e;
        }
#pragma unroll
        for (int off = 16; off; off >>= 1)
            sum += __shfl_xor_sync(0xffffffffu, sum, off);
        float inv = 1.0f / sum;
        float* attn_g = attn_out + (size_t)(bh * N_ + q0 + w) * N_;
#pragma unroll
        for (int i = 0; i < 8; i++) {
            float p = vals[i] * inv;
            row[lane + 32 * i] = p;
            __stcs(attn_g + lane + 32 * i, p);
        }
    }
    __syncthreads();

    // ---- Phase D: out = attn @ v, first 256 threads, f32x2 packed ----
    if (tid < 256) {
        const int dg = tid & 15;   // 4 dims each
        const int qq = tid >> 4;   // 1 q-row each
        const float* vrow = v + (size_t)(bh * N_) * DV + dg * 4;
        const float* arow = s_attn + qq * ATT_STRIDE;
        ull o0 = 0, o1 = 0;
#pragma unroll 4
        for (int kk = 0; kk < N_; kk++) {
            float a = arow[kk];                                    // broadcast LDS
            ull a2 = pk2(a, a);
            ulonglong2 vv = *(const ulonglong2*)(vrow + kk * DV);  // LDG.128
            o0 = fma2(a2, vv.x, o0);
            o1 = fma2(a2, vv.y, o1);
        }
        float4 o;
        upk2(o0, o.x, o.y);
        upk2(o1, o.z, o.w);
        __stcs((float4*)(out + (size_t)(bh * N_ + q0 + qq) * DV + dg * 4), o);
    }
}

extern "C" void kernel_launch(void* const* d_in, const int* in_sizes, int n_in,
                              void* d_out, int out_size)
{
    const float* q    = (const float*)d_in[0];
    const float* nk   = (const float*)d_in[1];
    const float* ek   = (const float*)d_in[2];
    const float* v    = (const float*)d_in[3];
    const int*   mask = (const int*)d_in[4];

    float* out  = (float*)d_out;                         // [4,8,256,64]
    float* attn = out + (size_t)B_ * H_ * N_ * DV;       // [4,8,256,256]

    dim3 grid(N_ / TQ, H_, B_);
    edge_attn_kernel<<<grid, NTHREADS>>>(q, nk, ek, v, mask, out, attn);
}